// round 9
// baseline (speedup 1.0000x reference)
#include <cuda_runtime.h>
#include <cuda_bf16.h>
#include <cstdint>

// out[b] = T[fwd_steps[b]-1] @ x[b];  B=128, D=1024, fp32.
// R9: pre-split fp32 -> bf16 hi/lo planes (Markidis), pure-bf16 3-product
// mma.sync GEMM, 2-stage cp.async pipeline (75.8KB smem -> 2 CTAs/SM).

#define DDIM 1024
#define BKF 32
#define NCH (DDIM / BKF)          // 32 chunks
#define NSTAGE 2

#define A_STR 80                  // bytes per A smem row (32 bf16 + 16 pad)
#define B_STR 272                 // bytes per B smem row (128 bf16 + 16 pad)
#define A_LO 10240                // A lo-plane offset within stage (128*80)
#define B_OFF 20480               // B base within stage
#define B_LO 8704                 // B lo-plane offset (32*272)
#define STAGE 37888               // 2*10240 + 2*8704
#define SMEM_TOTAL (NSTAGE * STAGE)  // 75776

// ---- device scratch: bf16 hi/lo planes ----
__device__ __align__(16) __nv_bfloat16 g_Thi[100ull * DDIM * DDIM];
__device__ __align__(16) __nv_bfloat16 g_Tlo[100ull * DDIM * DDIM];
__device__ __align__(16) __nv_bfloat16 g_Xhi[128ull * DDIM * DDIM];
__device__ __align__(16) __nv_bfloat16 g_Xlo[128ull * DDIM * DDIM];

__device__ __forceinline__ uint32_t smem_u32(const void* p) {
    uint32_t a;
    asm("{ .reg .u64 t; cvta.to.shared.u64 t, %1; cvt.u32.u64 %0, t; }" : "=r"(a) : "l"(p));
    return a;
}
__device__ __forceinline__ void cp16(uint32_t dst, const void* src) {
    asm volatile("cp.async.cg.shared.global [%0], [%1], 16;"
                 :: "r"(dst), "l"(src) : "memory");
}
__device__ __forceinline__ void ldsm4(uint32_t (&r)[4], uint32_t addr) {
    asm volatile("ldmatrix.sync.aligned.m8n8.x4.shared.b16 {%0,%1,%2,%3}, [%4];"
                 : "=r"(r[0]), "=r"(r[1]), "=r"(r[2]), "=r"(r[3]) : "r"(addr));
}
__device__ __forceinline__ void ldsm4t(uint32_t (&r)[4], uint32_t addr) {
    asm volatile("ldmatrix.sync.aligned.m8n8.x4.trans.shared.b16 {%0,%1,%2,%3}, [%4];"
                 : "=r"(r[0]), "=r"(r[1]), "=r"(r[2]), "=r"(r[3]) : "r"(addr));
}
__device__ __forceinline__ void mma_bf16(float (&d)[4], const uint32_t (&a)[4],
                                         uint32_t b0, uint32_t b1) {
    asm volatile(
        "mma.sync.aligned.m16n8k16.row.col.f32.bf16.bf16.f32 "
        "{%0,%1,%2,%3}, {%4,%5,%6,%7}, {%8,%9}, {%0,%1,%2,%3};"
        : "+f"(d[0]), "+f"(d[1]), "+f"(d[2]), "+f"(d[3])
        : "r"(a[0]), "r"(a[1]), "r"(a[2]), "r"(a[3]), "r"(b0), "r"(b1));
}

// ---- prepass: fp32 -> bf16 hi + bf16 lo (residual) ----
__device__ __forceinline__ void split2(float x, float y, uint32_t& hp, uint32_t& lp) {
    __nv_bfloat16 hx = __float2bfloat16_rn(x);
    __nv_bfloat16 hy = __float2bfloat16_rn(y);
    float rx = x - __bfloat162float(hx);
    float ry = y - __bfloat162float(hy);
    __nv_bfloat16 lx = __float2bfloat16_rn(rx);
    __nv_bfloat16 ly = __float2bfloat16_rn(ry);
    hp = (uint32_t)__bfloat16_as_ushort(hx) | ((uint32_t)__bfloat16_as_ushort(hy) << 16);
    lp = (uint32_t)__bfloat16_as_ushort(lx) | ((uint32_t)__bfloat16_as_ushort(ly) << 16);
}

__global__ __launch_bounds__(256) void split_T_kernel(const float* __restrict__ src) {
    const size_t i = (size_t)blockIdx.x * blockDim.x + threadIdx.x;  // float4 index
    float4 v = *reinterpret_cast<const float4*>(src + 4 * i);
    uint2 hi, lo;
    split2(v.x, v.y, hi.x, lo.x);
    split2(v.z, v.w, hi.y, lo.y);
    *reinterpret_cast<uint2*>(g_Thi + 4 * i) = hi;
    *reinterpret_cast<uint2*>(g_Tlo + 4 * i) = lo;
}
__global__ __launch_bounds__(256) void split_X_kernel(const float* __restrict__ src) {
    const size_t i = (size_t)blockIdx.x * blockDim.x + threadIdx.x;
    float4 v = *reinterpret_cast<const float4*>(src + 4 * i);
    uint2 hi, lo;
    split2(v.x, v.y, hi.x, lo.x);
    split2(v.z, v.w, hi.y, lo.y);
    *reinterpret_cast<uint2*>(g_Xhi + 4 * i) = hi;
    *reinterpret_cast<uint2*>(g_Xlo + 4 * i) = lo;
}

// ---- main GEMM ----
__device__ __forceinline__ void load_stage(
    uint32_t sb, int stage, int kc, int tid, int tm0, int tn0,
    const __nv_bfloat16* __restrict__ Ahi, const __nv_bfloat16* __restrict__ Alo,
    const __nv_bfloat16* __restrict__ Bhi, const __nv_bfloat16* __restrict__ Blo) {
    const uint32_t base = sb + (uint32_t)stage * STAGE;
    // A: 128 rows x 64B (32 bf16) per plane -> 512 x 16B chunks, 2 per thread
    #pragma unroll
    for (int j = 0; j < 2; ++j) {
        const int i = tid * 2 + j;
        const int row = i >> 2, c16 = i & 3;
        const uint32_t dst = base + row * A_STR + c16 * 16;
        const size_t s = (size_t)(tm0 + row) * DDIM + kc + c16 * 8;
        cp16(dst, Ahi + s);
        cp16(dst + A_LO, Alo + s);
    }
    // B: 32 rows x 256B per plane -> 512 x 16B chunks, 2 per thread
    #pragma unroll
    for (int j = 0; j < 2; ++j) {
        const int i = tid * 2 + j;
        const int row = i >> 4, ch = i & 15;
        const uint32_t dst = base + B_OFF + row * B_STR + ch * 16;
        const size_t s = (size_t)(kc + row) * DDIM + tn0 + ch * 8;
        cp16(dst, Bhi + s);
        cp16(dst + B_LO, Blo + s);
    }
}

// one k16 step: 12 ldmatrix + 48 mma (3 products, 4m x 4n tiles)
__device__ __forceinline__ void do_k16(uint32_t sb, uint32_t stg, int k16,
                                       int warp_m, int warp_n, int lane,
                                       float (&acc)[4][4][4]) {
    const uint32_t lrow = lane & 15;
    const uint32_t lsel = lane >> 4;
    const uint32_t a_off = sb + stg + (warp_m * 64 + lrow) * A_STR +
                           (k16 * 16 + lsel * 8) * 2;
    const uint32_t b_off = sb + stg + B_OFF + (k16 * 16 + lrow) * B_STR +
                           (warp_n * 32 + lsel * 8) * 2;

    uint32_t bh[2][4], bl[2][4], a[4][4];
    #pragma unroll
    for (int g = 0; g < 2; ++g) ldsm4t(bh[g], b_off + g * 32);
    #pragma unroll
    for (int g = 0; g < 2; ++g) ldsm4t(bl[g], b_off + B_LO + g * 32);
    #pragma unroll
    for (int mt = 0; mt < 4; ++mt) ldsm4(a[mt], a_off + mt * (16 * A_STR));

    #pragma unroll
    for (int mt = 0; mt < 4; ++mt)
        #pragma unroll
        for (int nt = 0; nt < 4; ++nt)
            mma_bf16(acc[mt][nt], a[mt], bh[nt >> 1][(nt & 1) * 2], bh[nt >> 1][(nt & 1) * 2 + 1]);
    #pragma unroll
    for (int mt = 0; mt < 4; ++mt)
        #pragma unroll
        for (int nt = 0; nt < 4; ++nt)
            mma_bf16(acc[mt][nt], a[mt], bl[nt >> 1][(nt & 1) * 2], bl[nt >> 1][(nt & 1) * 2 + 1]);
    #pragma unroll
    for (int mt = 0; mt < 4; ++mt) ldsm4(a[mt], a_off + A_LO + mt * (16 * A_STR));
    #pragma unroll
    for (int mt = 0; mt < 4; ++mt)
        #pragma unroll
        for (int nt = 0; nt < 4; ++nt)
            mma_bf16(acc[mt][nt], a[mt], bh[nt >> 1][(nt & 1) * 2], bh[nt >> 1][(nt & 1) * 2 + 1]);
}

__global__ __launch_bounds__(256, 2) void bgemm_mma_kernel(
    const int* __restrict__ steps32,
    float*     __restrict__ Out) {
    extern __shared__ char smem[];
    const uint32_t sb = smem_u32(smem);
    const int tid  = threadIdx.x;
    const int lane = tid & 31;
    const int wid  = tid >> 5;
    const int warp_m = wid & 1;
    const int warp_n = wid >> 1;

    const int b = blockIdx.z;
    const bool is64 = (steps32[1] == 0);
    const int kidx = (is64 ? steps32[2 * b] : steps32[b]) - 1;

    const __nv_bfloat16* __restrict__ Ahi = g_Thi + ((size_t)kidx << 20);
    const __nv_bfloat16* __restrict__ Alo = g_Tlo + ((size_t)kidx << 20);
    const __nv_bfloat16* __restrict__ Bhi = g_Xhi + ((size_t)b << 20);
    const __nv_bfloat16* __restrict__ Blo = g_Xlo + ((size_t)b << 20);
    float* __restrict__ Cg = Out + ((size_t)b << 20);

    const int tm0 = blockIdx.y * 128;
    const int tn0 = blockIdx.x * 128;

    float acc[4][4][4];
    #pragma unroll
    for (int i = 0; i < 4; ++i)
        #pragma unroll
        for (int j = 0; j < 4; ++j)
            #pragma unroll
            for (int q = 0; q < 4; ++q)
                acc[i][j][q] = 0.0f;

    // prologue: stage 0 in flight
    load_stage(sb, 0, 0, tid, tm0, tn0, Ahi, Alo, Bhi, Blo);
    asm volatile("cp.async.commit_group;" ::: "memory");

    for (int c = 0; c < NCH; ++c) {
        // stage c arrived (group issued last iter or prologue)
        asm volatile("cp.async.wait_group 0;" ::: "memory");
        __syncthreads();
        // everyone has finished reading stage c-1 -> refill that buffer with c+1;
        // this load overlaps the compute below.
        if (c + 1 < NCH)
            load_stage(sb, (c + 1) & 1, (c + 1) * BKF, tid, tm0, tn0,
                       Ahi, Alo, Bhi, Blo);
        asm volatile("cp.async.commit_group;" ::: "memory");

        const uint32_t stg = (uint32_t)(c & 1) * STAGE;
        do_k16(sb, stg, 0, warp_m, warp_n, lane, acc);
        do_k16(sb, stg, 1, warp_m, warp_n, lane, acc);
    }

    // epilogue
    const int g = lane >> 2;
    const int t = lane & 3;
    #pragma unroll
    for (int mt = 0; mt < 4; ++mt) {
        #pragma unroll
        for (int nt = 0; nt < 4; ++nt) {
            const int row = tm0 + warp_m * 64 + mt * 16 + g;
            const int col = tn0 + warp_n * 32 + nt * 8 + t * 2;
            *reinterpret_cast<float2*>(Cg + (size_t)row * DDIM + col) =
                make_float2(acc[mt][nt][0], acc[mt][nt][1]);
            *reinterpret_cast<float2*>(Cg + (size_t)(row + 8) * DDIM + col) =
                make_float2(acc[mt][nt][2], acc[mt][nt][3]);
        }
    }
}

extern "C" void kernel_launch(void* const* d_in, const int* in_sizes, int n_in,
                              void* d_out, int out_size) {
    const float* x     = (const float*)d_in[0];
    const int*   steps = (const int*)d_in[1];
    const float* T     = (const float*)d_in[2];
    float* out = (float*)d_out;

    // prepass: split into bf16 hi/lo planes
    {
        const size_t nT4 = 100ull * DDIM * DDIM / 4;
        const size_t nX4 = 128ull * DDIM * DDIM / 4;
        split_T_kernel<<<(unsigned)(nT4 / 256), 256>>>(T);
        split_X_kernel<<<(unsigned)(nX4 / 256), 256>>>(x);
    }

    cudaFuncSetAttribute(bgemm_mma_kernel,
                         cudaFuncAttributeMaxDynamicSharedMemorySize, SMEM_TOTAL);
    dim3 grid(DDIM / 128, DDIM / 128, 128);  // (8, 8, 128)
    bgemm_mma_kernel<<<grid, 256, SMEM_TOTAL>>>(steps, out);
}

// round 10
// speedup vs baseline: 1.4951x; 1.4951x over previous
#include <cuda_runtime.h>
#include <cuda_fp16.h>
#include <cstdint>

// out[b] = T[fwd_steps[b]-1] @ x[b];  B=128, D=1024, fp32.
// R10: single-pass fp16 mma.sync (norm-based rel_err budget allows ~5e-4).
// Prepass converts T and x to fp16 planes; GEMM is a pure fp16 pipeline:
// 128x128 tile, BK=32, 3-stage cp.async, 8 warps (2m x 4n), warp tile 64x32.

#define DDIM 1024
#define BKF 32
#define NCH (DDIM / BKF)          // 32 chunks
#define NSTAGE 3

#define A_STR 80                  // bytes per A smem row (32 fp16 + 16 pad)
#define B_STR 272                 // bytes per B smem row (128 fp16 + 16 pad)
#define B_OFF 10240               // B base within stage (128*80)
#define STAGE 18944               // 10240 + 32*272
#define SMEM_TOTAL (NSTAGE * STAGE)  // 56832

// ---- device scratch: fp16 planes ----
__device__ __align__(16) __half g_Th[100ull * DDIM * DDIM];   // 200 MB
__device__ __align__(16) __half g_Xh[128ull * DDIM * DDIM];   // 256 MB

__device__ __forceinline__ uint32_t smem_u32(const void* p) {
    uint32_t a;
    asm("{ .reg .u64 t; cvta.to.shared.u64 t, %1; cvt.u32.u64 %0, t; }" : "=r"(a) : "l"(p));
    return a;
}
__device__ __forceinline__ void cp16(uint32_t dst, const void* src) {
    asm volatile("cp.async.cg.shared.global [%0], [%1], 16;"
                 :: "r"(dst), "l"(src) : "memory");
}
__device__ __forceinline__ void ldsm4(uint32_t (&r)[4], uint32_t addr) {
    asm volatile("ldmatrix.sync.aligned.m8n8.x4.shared.b16 {%0,%1,%2,%3}, [%4];"
                 : "=r"(r[0]), "=r"(r[1]), "=r"(r[2]), "=r"(r[3]) : "r"(addr));
}
__device__ __forceinline__ void ldsm4t(uint32_t (&r)[4], uint32_t addr) {
    asm volatile("ldmatrix.sync.aligned.m8n8.x4.trans.shared.b16 {%0,%1,%2,%3}, [%4];"
                 : "=r"(r[0]), "=r"(r[1]), "=r"(r[2]), "=r"(r[3]) : "r"(addr));
}
__device__ __forceinline__ void mma_f16(float (&d)[4], const uint32_t (&a)[4],
                                        uint32_t b0, uint32_t b1) {
    asm volatile(
        "mma.sync.aligned.m16n8k16.row.col.f32.f16.f16.f32 "
        "{%0,%1,%2,%3}, {%4,%5,%6,%7}, {%8,%9}, {%0,%1,%2,%3};"
        : "+f"(d[0]), "+f"(d[1]), "+f"(d[2]), "+f"(d[3])
        : "r"(a[0]), "r"(a[1]), "r"(a[2]), "r"(a[3]), "r"(b0), "r"(b1));
}

// ---- prepass: fp32 -> fp16 ----
__global__ __launch_bounds__(256) void cvt_T_kernel(const float* __restrict__ src) {
    const size_t i = (size_t)blockIdx.x * blockDim.x + threadIdx.x;  // float4 index
    float4 v = *reinterpret_cast<const float4*>(src + 4 * i);
    __half2 h0 = __floats2half2_rn(v.x, v.y);
    __half2 h1 = __floats2half2_rn(v.z, v.w);
    *reinterpret_cast<uint2*>(g_Th + 4 * i) =
        make_uint2(*reinterpret_cast<uint32_t*>(&h0), *reinterpret_cast<uint32_t*>(&h1));
}
__global__ __launch_bounds__(256) void cvt_X_kernel(const float* __restrict__ src) {
    const size_t i = (size_t)blockIdx.x * blockDim.x + threadIdx.x;
    float4 v = *reinterpret_cast<const float4*>(src + 4 * i);
    __half2 h0 = __floats2half2_rn(v.x, v.y);
    __half2 h1 = __floats2half2_rn(v.z, v.w);
    *reinterpret_cast<uint2*>(g_Xh + 4 * i) =
        make_uint2(*reinterpret_cast<uint32_t*>(&h0), *reinterpret_cast<uint32_t*>(&h1));
}

// ---- main GEMM ----
__device__ __forceinline__ void load_stage(
    uint32_t sb, int stage, int kc, int tid, int tm0, int tn0,
    const __half* __restrict__ Ah, const __half* __restrict__ Bh) {
    const uint32_t base = sb + (uint32_t)stage * STAGE;
    // A: 128 rows x 64B -> 512 x 16B chunks, 2 per thread
    #pragma unroll
    for (int j = 0; j < 2; ++j) {
        const int i = tid * 2 + j;
        const int row = i >> 2, c16 = i & 3;
        cp16(base + row * A_STR + c16 * 16,
             Ah + (size_t)(tm0 + row) * DDIM + kc + c16 * 8);
    }
    // B: 32 rows x 256B -> 512 x 16B chunks, 2 per thread
    #pragma unroll
    for (int j = 0; j < 2; ++j) {
        const int i = tid * 2 + j;
        const int row = i >> 4, ch = i & 15;
        cp16(base + B_OFF + row * B_STR + ch * 16,
             Bh + (size_t)(kc + row) * DDIM + tn0 + ch * 8);
    }
}

// one k16 step: 6 ldmatrix + 16 mma (4m x 4n tiles)
__device__ __forceinline__ void do_k16(uint32_t sb, uint32_t stg, int k16,
                                       int warp_m, int warp_n, int lane,
                                       float (&acc)[4][4][4]) {
    const uint32_t lrow = lane & 15;
    const uint32_t lsel = lane >> 4;
    const uint32_t a_off = sb + stg + (warp_m * 64 + lrow) * A_STR +
                           (k16 * 16 + lsel * 8) * 2;
    const uint32_t b_off = sb + stg + B_OFF + (k16 * 16 + lrow) * B_STR +
                           (warp_n * 32 + lsel * 8) * 2;

    uint32_t bh[2][4], a[4][4];
    #pragma unroll
    for (int g = 0; g < 2; ++g) ldsm4t(bh[g], b_off + g * 32);
    #pragma unroll
    for (int mt = 0; mt < 4; ++mt) ldsm4(a[mt], a_off + mt * (16 * A_STR));

    #pragma unroll
    for (int mt = 0; mt < 4; ++mt)
        #pragma unroll
        for (int nt = 0; nt < 4; ++nt)
            mma_f16(acc[mt][nt], a[mt],
                    bh[nt >> 1][(nt & 1) * 2], bh[nt >> 1][(nt & 1) * 2 + 1]);
}

__global__ __launch_bounds__(256, 2) void bgemm_mma_kernel(
    const int* __restrict__ steps32,
    float*     __restrict__ Out) {
    extern __shared__ char smem[];
    const uint32_t sb = smem_u32(smem);
    const int tid  = threadIdx.x;
    const int lane = tid & 31;
    const int wid  = tid >> 5;
    const int warp_m = wid & 1;
    const int warp_n = wid >> 1;

    const int b = blockIdx.z;
    const bool is64 = (steps32[1] == 0);
    const int kidx = (is64 ? steps32[2 * b] : steps32[b]) - 1;

    const __half* __restrict__ Ah = g_Th + ((size_t)kidx << 20);
    const __half* __restrict__ Bh = g_Xh + ((size_t)b << 20);
    float* __restrict__ Cg = Out + ((size_t)b << 20);

    const int tm0 = blockIdx.y * 128;
    const int tn0 = blockIdx.x * 128;

    float acc[4][4][4];
    #pragma unroll
    for (int i = 0; i < 4; ++i)
        #pragma unroll
        for (int j = 0; j < 4; ++j)
            #pragma unroll
            for (int q = 0; q < 4; ++q)
                acc[i][j][q] = 0.0f;

    // prologue: stages 0 and 1 in flight
    load_stage(sb, 0, 0, tid, tm0, tn0, Ah, Bh);
    asm volatile("cp.async.commit_group;" ::: "memory");
    load_stage(sb, 1, BKF, tid, tm0, tn0, Ah, Bh);
    asm volatile("cp.async.commit_group;" ::: "memory");

    for (int c = 0; c < NCH; ++c) {
        // oldest outstanding group (stage c) complete; <=1 group stays in flight
        asm volatile("cp.async.wait_group 1;" ::: "memory");
        __syncthreads();
        // refill the stage read at iter c-1 (c+2 == c-1 mod 3)
        if (c + 2 < NCH)
            load_stage(sb, (c + 2) % NSTAGE, (c + 2) * BKF, tid, tm0, tn0, Ah, Bh);
        asm volatile("cp.async.commit_group;" ::: "memory");

        const uint32_t stg = (uint32_t)(c % NSTAGE) * STAGE;
        do_k16(sb, stg, 0, warp_m, warp_n, lane, acc);
        do_k16(sb, stg, 1, warp_m, warp_n, lane, acc);
    }

    // epilogue
    const int g = lane >> 2;
    const int t = lane & 3;
    #pragma unroll
    for (int mt = 0; mt < 4; ++mt) {
        #pragma unroll
        for (int nt = 0; nt < 4; ++nt) {
            const int row = tm0 + warp_m * 64 + mt * 16 + g;
            const int col = tn0 + warp_n * 32 + nt * 8 + t * 2;
            *reinterpret_cast<float2*>(Cg + (size_t)row * DDIM + col) =
                make_float2(acc[mt][nt][0], acc[mt][nt][1]);
            *reinterpret_cast<float2*>(Cg + (size_t)(row + 8) * DDIM + col) =
                make_float2(acc[mt][nt][2], acc[mt][nt][3]);
        }
    }
}

extern "C" void kernel_launch(void* const* d_in, const int* in_sizes, int n_in,
                              void* d_out, int out_size) {
    const float* x     = (const float*)d_in[0];
    const int*   steps = (const int*)d_in[1];
    const float* T     = (const float*)d_in[2];
    float* out = (float*)d_out;

    // prepass: fp32 -> fp16 planes
    {
        const size_t nT4 = 100ull * DDIM * DDIM / 4;   // 26,214,400
        const size_t nX4 = 128ull * DDIM * DDIM / 4;   // 33,554,432
        cvt_T_kernel<<<(unsigned)(nT4 / 256), 256>>>(T);
        cvt_X_kernel<<<(unsigned)(nX4 / 256), 256>>>(x);
    }

    cudaFuncSetAttribute(bgemm_mma_kernel,
                         cudaFuncAttributeMaxDynamicSharedMemorySize, SMEM_TOTAL);
    dim3 grid(DDIM / 128, DDIM / 128, 128);  // (8, 8, 128)
    bgemm_mma_kernel<<<grid, 256, SMEM_TOTAL>>>(steps, out);
}

// round 11
// speedup vs baseline: 1.8996x; 1.2705x over previous
#include <cuda_runtime.h>
#include <cuda_fp16.h>
#include <cstdint>

// out[b] = T[fwd_steps[b]-1] @ x[b];  B=128, D=1024, fp32.
// R11: single-pass fp16 mma.sync, CTA tile 128x256, warp tile 64x64
// (8 warps, 2m x 4n), 3-stage cp.async. Prepass converts T,x to fp16 planes.

#define DDIM 1024
#define BKF 32
#define NCH (DDIM / BKF)          // 32 chunks
#define NSTAGE 3
#define TM 128
#define TN 256

#define A_STR 80                  // bytes per A smem row (32 fp16 + 16 pad)
#define B_STR 528                 // bytes per B smem row (256 fp16 + 16 pad)
#define B_OFF 10240               // B base within stage (128*80)
#define STAGE 27136               // 10240 + 32*528
#define SMEM_TOTAL (NSTAGE * STAGE)  // 81408

// ---- device scratch: fp16 planes ----
__device__ __align__(16) __half g_Th[100ull * DDIM * DDIM];   // 200 MB
__device__ __align__(16) __half g_Xh[128ull * DDIM * DDIM];   // 256 MB

__device__ __forceinline__ uint32_t smem_u32(const void* p) {
    uint32_t a;
    asm("{ .reg .u64 t; cvta.to.shared.u64 t, %1; cvt.u32.u64 %0, t; }" : "=r"(a) : "l"(p));
    return a;
}
__device__ __forceinline__ void cp16(uint32_t dst, const void* src) {
    asm volatile("cp.async.cg.shared.global [%0], [%1], 16;"
                 :: "r"(dst), "l"(src) : "memory");
}
__device__ __forceinline__ void ldsm4(uint32_t (&r)[4], uint32_t addr) {
    asm volatile("ldmatrix.sync.aligned.m8n8.x4.shared.b16 {%0,%1,%2,%3}, [%4];"
                 : "=r"(r[0]), "=r"(r[1]), "=r"(r[2]), "=r"(r[3]) : "r"(addr));
}
__device__ __forceinline__ void ldsm4t(uint32_t (&r)[4], uint32_t addr) {
    asm volatile("ldmatrix.sync.aligned.m8n8.x4.trans.shared.b16 {%0,%1,%2,%3}, [%4];"
                 : "=r"(r[0]), "=r"(r[1]), "=r"(r[2]), "=r"(r[3]) : "r"(addr));
}
__device__ __forceinline__ void mma_f16(float (&d)[4], const uint32_t (&a)[4],
                                        uint32_t b0, uint32_t b1) {
    asm volatile(
        "mma.sync.aligned.m16n8k16.row.col.f32.f16.f16.f32 "
        "{%0,%1,%2,%3}, {%4,%5,%6,%7}, {%8,%9}, {%0,%1,%2,%3};"
        : "+f"(d[0]), "+f"(d[1]), "+f"(d[2]), "+f"(d[3])
        : "r"(a[0]), "r"(a[1]), "r"(a[2]), "r"(a[3]), "r"(b0), "r"(b1));
}

// ---- prepass: fp32 -> fp16 ----
__global__ __launch_bounds__(256) void cvt_T_kernel(const float* __restrict__ src) {
    const size_t i = (size_t)blockIdx.x * blockDim.x + threadIdx.x;  // float4 index
    float4 v = *reinterpret_cast<const float4*>(src + 4 * i);
    __half2 h0 = __floats2half2_rn(v.x, v.y);
    __half2 h1 = __floats2half2_rn(v.z, v.w);
    *reinterpret_cast<uint2*>(g_Th + 4 * i) =
        make_uint2(*reinterpret_cast<uint32_t*>(&h0), *reinterpret_cast<uint32_t*>(&h1));
}
__global__ __launch_bounds__(256) void cvt_X_kernel(const float* __restrict__ src) {
    const size_t i = (size_t)blockIdx.x * blockDim.x + threadIdx.x;
    float4 v = *reinterpret_cast<const float4*>(src + 4 * i);
    __half2 h0 = __floats2half2_rn(v.x, v.y);
    __half2 h1 = __floats2half2_rn(v.z, v.w);
    *reinterpret_cast<uint2*>(g_Xh + 4 * i) =
        make_uint2(*reinterpret_cast<uint32_t*>(&h0), *reinterpret_cast<uint32_t*>(&h1));
}

// ---- main GEMM ----
__device__ __forceinline__ void load_stage(
    uint32_t sb, int stage, int kc, int tid, int tm0, int tn0,
    const __half* __restrict__ Ah, const __half* __restrict__ Bh) {
    const uint32_t base = sb + (uint32_t)stage * STAGE;
    // A: 128 rows x 64B -> 512 x 16B chunks, 2 per thread
    #pragma unroll
    for (int j = 0; j < 2; ++j) {
        const int i = tid * 2 + j;
        const int row = i >> 2, c16 = i & 3;
        cp16(base + row * A_STR + c16 * 16,
             Ah + (size_t)(tm0 + row) * DDIM + kc + c16 * 8);
    }
    // B: 32 rows x 512B -> 1024 x 16B chunks, 4 per thread
    #pragma unroll
    for (int j = 0; j < 4; ++j) {
        const int i = tid * 4 + j;
        const int row = i >> 5, ch = i & 31;
        cp16(base + B_OFF + row * B_STR + ch * 16,
             Bh + (size_t)(kc + row) * DDIM + tn0 + ch * 8);
    }
}

// one k16 step: 8 ldmatrix + 32 mma (4m x 8n tiles of m16n8)
__device__ __forceinline__ void do_k16(uint32_t sb, uint32_t stg, int k16,
                                       int warp_m, int warp_n, int lane,
                                       float (&acc)[4][8][4]) {
    const uint32_t lrow = lane & 15;
    const uint32_t lsel = lane >> 4;
    const uint32_t a_off = sb + stg + (warp_m * 64 + lrow) * A_STR +
                           (k16 * 16 + lsel * 8) * 2;
    const uint32_t b_off = sb + stg + B_OFF + (k16 * 16 + lrow) * B_STR +
                           (warp_n * 64 + lsel * 8) * 2;

    uint32_t bh[4][4], a[4][4];
    #pragma unroll
    for (int g = 0; g < 4; ++g) ldsm4t(bh[g], b_off + g * 32);
    #pragma unroll
    for (int mt = 0; mt < 4; ++mt) ldsm4(a[mt], a_off + mt * (16 * A_STR));

    #pragma unroll
    for (int mt = 0; mt < 4; ++mt)
        #pragma unroll
        for (int nt = 0; nt < 8; ++nt)
            mma_f16(acc[mt][nt], a[mt],
                    bh[nt >> 1][(nt & 1) * 2], bh[nt >> 1][(nt & 1) * 2 + 1]);
}

__global__ __launch_bounds__(256) void bgemm_mma_kernel(
    const int* __restrict__ steps32,
    float*     __restrict__ Out) {
    extern __shared__ char smem[];
    const uint32_t sb = smem_u32(smem);
    const int tid  = threadIdx.x;
    const int lane = tid & 31;
    const int wid  = tid >> 5;
    const int warp_m = wid & 1;   // 2 warps over M (64 each)
    const int warp_n = wid >> 1;  // 4 warps over N (64 each)

    const int b = blockIdx.z;
    const bool is64 = (steps32[1] == 0);
    const int kidx = (is64 ? steps32[2 * b] : steps32[b]) - 1;

    const __half* __restrict__ Ah = g_Th + ((size_t)kidx << 20);
    const __half* __restrict__ Bh = g_Xh + ((size_t)b << 20);
    float* __restrict__ Cg = Out + ((size_t)b << 20);

    const int tm0 = blockIdx.y * TM;
    const int tn0 = blockIdx.x * TN;

    float acc[4][8][4];
    #pragma unroll
    for (int i = 0; i < 4; ++i)
        #pragma unroll
        for (int j = 0; j < 8; ++j)
            #pragma unroll
            for (int q = 0; q < 4; ++q)
                acc[i][j][q] = 0.0f;

    // prologue: stages 0 and 1 in flight
    load_stage(sb, 0, 0, tid, tm0, tn0, Ah, Bh);
    asm volatile("cp.async.commit_group;" ::: "memory");
    load_stage(sb, 1, BKF, tid, tm0, tn0, Ah, Bh);
    asm volatile("cp.async.commit_group;" ::: "memory");

    for (int c = 0; c < NCH; ++c) {
        asm volatile("cp.async.wait_group 1;" ::: "memory");
        __syncthreads();
        // refill the stage read at iter c-1 (c+2 == c-1 mod 3)
        if (c + 2 < NCH)
            load_stage(sb, (c + 2) % NSTAGE, (c + 2) * BKF, tid, tm0, tn0, Ah, Bh);
        asm volatile("cp.async.commit_group;" ::: "memory");

        const uint32_t stg = (uint32_t)(c % NSTAGE) * STAGE;
        do_k16(sb, stg, 0, warp_m, warp_n, lane, acc);
        do_k16(sb, stg, 1, warp_m, warp_n, lane, acc);
    }

    // epilogue
    const int g = lane >> 2;
    const int t = lane & 3;
    #pragma unroll
    for (int mt = 0; mt < 4; ++mt) {
        #pragma unroll
        for (int nt = 0; nt < 8; ++nt) {
            const int row = tm0 + warp_m * 64 + mt * 16 + g;
            const int col = tn0 + warp_n * 64 + nt * 8 + t * 2;
            *reinterpret_cast<float2*>(Cg + (size_t)row * DDIM + col) =
                make_float2(acc[mt][nt][0], acc[mt][nt][1]);
            *reinterpret_cast<float2*>(Cg + (size_t)(row + 8) * DDIM + col) =
                make_float2(acc[mt][nt][2], acc[mt][nt][3]);
        }
    }
}

extern "C" void kernel_launch(void* const* d_in, const int* in_sizes, int n_in,
                              void* d_out, int out_size) {
    const float* x     = (const float*)d_in[0];
    const int*   steps = (const int*)d_in[1];
    const float* T     = (const float*)d_in[2];
    float* out = (float*)d_out;

    // prepass: fp32 -> fp16 planes
    {
        const size_t nT4 = 100ull * DDIM * DDIM / 4;
        const size_t nX4 = 128ull * DDIM * DDIM / 4;
        cvt_T_kernel<<<(unsigned)(nT4 / 256), 256>>>(T);
        cvt_X_kernel<<<(unsigned)(nX4 / 256), 256>>>(x);
    }

    cudaFuncSetAttribute(bgemm_mma_kernel,
                         cudaFuncAttributeMaxDynamicSharedMemorySize, SMEM_TOTAL);
    dim3 grid(DDIM / TN, DDIM / TM, 128);  // (4, 8, 128)
    bgemm_mma_kernel<<<grid, 256, SMEM_TOTAL>>>(steps, out);
}